// round 4
// baseline (speedup 1.0000x reference)
#include <cuda_runtime.h>
#include <cstdint>
#include <cstddef>

// Problem constants
#define NB 32
#define NT 512
#define NI 256
#define NH 512

// -------------------- device scratch (no allocations allowed) --------------------
// xp layout: [d][t][row(2048)][b(32)], row = unit*4 + gate  (gate: 0=i,1=f,2=g,3=o)
__device__ float    g_xp[2u * 512u * 2048u * 32u];   // 268 MB
// h double buffer per direction: [d][buf][k(512)][b(32)]
__device__ float    g_h[2 * 2 * 512 * 32];
__device__ unsigned g_bar_count;

// -------------------- f32x2 helpers --------------------
__device__ __forceinline__ unsigned long long pk2(float a, float b) {
    unsigned long long r;
    asm("mov.b64 %0, {%1,%2};" : "=l"(r) : "f"(a), "f"(b));
    return r;
}
__device__ __forceinline__ void upk2(unsigned long long v, float& a, float& b) {
    asm("mov.b64 {%0,%1}, %2;" : "=f"(a), "=f"(b) : "l"(v));
}
__device__ __forceinline__ void fma2(unsigned long long& d, unsigned long long a, unsigned long long b) {
    asm("fma.rn.f32x2 %0, %1, %2, %0;" : "+l"(d) : "l"(a), "l"(b));
}
__device__ __forceinline__ void add2(unsigned long long& d, unsigned long long a) {
    asm("add.rn.f32x2 %0, %0, %1;" : "+l"(d) : "l"(a));
}

__device__ __forceinline__ float sigmoidf_(float x) {
    return 1.0f / (1.0f + __expf(-x));
}
__device__ __forceinline__ float tanh_fast(float x) {
    float r;
    asm("tanh.approx.f32 %0, %1;" : "=f"(r) : "f"(x));
    return r;
}

// ==================================================================================
// init: zero h buffers, reset barrier counter (runs every launch -> deterministic)
// ==================================================================================
__global__ void k_init() {
    int t = blockIdx.x * blockDim.x + threadIdx.x;
    if (t == 0) g_bar_count = 0u;
    if (t < 2 * 2 * 512 * 32) g_h[t] = 0.0f;
}

// ==================================================================================
// Phase A: input projections.  xp[d][t][row][b] = sum_i x[b][t][i]*W_ih[d][wrow][i] + bias
// where row = unit*4+gate and wrow = gate*512 + unit  (wrow = (row&3)*512 + (row>>2)).
// Block: (t-chunk of 32) x (64 rows) x (direction).  256 threads, 8 warps.
// Warp w computes local rows w*8..w*8+7 (4 f32x2 pairs), lane = batch.
// ==================================================================================
#define XPROJ_SMEM (65536 + 64 * 33 * 16)  // 64KB packed weights + padded x tile

__global__ __launch_bounds__(256, 2) void k_xproj(
    const float* __restrict__ x,
    const float* __restrict__ Wf, const float* __restrict__ bf,
    const float* __restrict__ Wb, const float* __restrict__ bb)
{
    extern __shared__ char smem[];
    unsigned long long* sW = (unsigned long long*)smem;        // [256][32] u64 pairs (64KB)
    float*              fW = (float*)smem;                     // alias: fW[k*64 + lr]
    float4*             sX = (float4*)(smem + 65536);          // [k4(64)*33 + b] padded

    const int d    = blockIdx.z;
    const float* W    = d ? Wb : Wf;
    const float* bias = d ? bb : bf;
    const int R0   = blockIdx.y * 64;
    const int t0   = blockIdx.x * 32;
    const int tid  = threadIdx.x;
    const int lane = tid & 31;
    const int w    = tid >> 5;

    // ---- load + pack weight slice: fW[k*64 + lr] = W[wrow(R0+lr)][k]
    {
        int lr   = tid & 63;
        int kb   = (tid >> 6) * 64;
        int grow = R0 + lr;
        int wrow = ((grow & 3) << 9) + (grow >> 2);
        const float* src = W + wrow * 256 + kb;
        #pragma unroll 8
        for (int k = 0; k < 64; k++)
            fW[(kb + k) * 64 + lr] = src[k];
    }

    // ---- per-thread bias values for its 8 rows (hoisted out of t loop)
    float bv[8];
    #pragma unroll
    for (int r = 0; r < 8; r++) {
        int grow = R0 + w * 8 + r;
        bv[r] = bias[((grow & 3) << 9) + (grow >> 2)];
    }
    __syncthreads();

    for (int tl = 0; tl < 32; tl++) {
        int t = t0 + tl;
        __syncthreads();  // previous tile fully consumed
        // ---- load x tile: sX[k4*33 + b] = x[b][t][k4*4 .. +3]
        #pragma unroll
        for (int bi = 0; bi < 4; bi++) {
            int b = w + bi * 8;
            #pragma unroll
            for (int kh = 0; kh < 2; kh++) {
                int k4 = kh * 32 + lane;
                float4 v = *(const float4*)(x + ((size_t)(b * 512 + t)) * 256 + k4 * 4);
                sX[k4 * 33 + b] = v;
            }
        }
        __syncthreads();

        unsigned long long acc0 = 0, acc1 = 0, acc2 = 0, acc3 = 0;
        const unsigned long long* wbase = sW + w * 4;
        #pragma unroll 4
        for (int k4 = 0; k4 < 64; k4++) {
            float4 xv = sX[k4 * 33 + lane];
            #pragma unroll
            for (int kk = 0; kk < 4; kk++) {
                float xs = (&xv.x)[kk];
                unsigned long long hh = pk2(xs, xs);
                const unsigned long long* wp = wbase + (k4 * 4 + kk) * 32;
                ulonglong2 wa = *(const ulonglong2*)(wp);
                ulonglong2 wc = *(const ulonglong2*)(wp + 2);
                fma2(acc0, hh, wa.x);
                fma2(acc1, hh, wa.y);
                fma2(acc2, hh, wc.x);
                fma2(acc3, hh, wc.y);
            }
        }

        // ---- store 8 rows (coalesced over lanes = batch)
        float* outp = g_xp + ((((size_t)d * 512 + t) * 2048) + R0) * 32 + lane;
        float f0, f1;
        upk2(acc0, f0, f1);
        outp[(w * 8 + 0) * 32] = f0 + bv[0];
        outp[(w * 8 + 1) * 32] = f1 + bv[1];
        upk2(acc1, f0, f1);
        outp[(w * 8 + 2) * 32] = f0 + bv[2];
        outp[(w * 8 + 3) * 32] = f1 + bv[3];
        upk2(acc2, f0, f1);
        outp[(w * 8 + 4) * 32] = f0 + bv[4];
        outp[(w * 8 + 5) * 32] = f1 + bv[5];
        upk2(acc3, f0, f1);
        outp[(w * 8 + 6) * 32] = f0 + bv[6];
        outp[(w * 8 + 7) * 32] = f1 + bv[7];
    }
}

// ==================================================================================
// Phase B: persistent recurrent kernel (v2: 512 threads / 16 warps for latency hiding).
// 128 blocks, 192KB smem => 1 block/SM => all co-resident, barrier safe.
// Block bid: d = bid>>6, owns hidden units j0 = (bid&63)*8 .. +8 of that direction.
// Compute: warp w handles k-range [32w, 32w+32) for all 8 units x 4 gates (f32x2),
// lane = batch. Cross-warp (16-way) reduce via smem.
// Finalize: tid<256, warp fw = unit, lane = batch; c stays in a register.
// xp for step s+1 is prefetched BEFORE the grid barrier (DRAM latency overlaps spin).
// ==================================================================================
#define RECUR_SMEM (65536 + 65536 + 65536)  // W_hh pairs + h + reduce staging (192KB)

__global__ __launch_bounds__(512, 1) void k_recur(
    const float* __restrict__ Whf,
    const float* __restrict__ Whb,
    float* __restrict__ out)
{
    extern __shared__ char smem[];
    ulonglong2*         wS  = (ulonglong2*)smem;                      // [512*8]  64KB
    float*              hS  = (float*)(smem + 65536);                 // [512*32] 64KB
    unsigned long long* red = (unsigned long long*)(smem + 131072);   // [16][8][2][32] 64KB

    const int bid  = blockIdx.x;
    const int d    = bid >> 6;
    const int j0   = (bid & 63) * 8;
    const int tid  = threadIdx.x;
    const int lane = tid & 31;
    const int w    = tid >> 5;
    const int nb   = gridDim.x;
    const float* Wh = d ? Whb : Whf;

    // ---- load + pack W_hh slice: wS[k*8+j] = { (wi,wf), (wg,wo) } for unit j0+j
    for (int idx = tid; idx < 512 * 8; idx += 512) {
        int k  = idx >> 3;
        int j  = idx & 7;
        int jg = j0 + j;
        float wi = Wh[((0 * 512) + jg) * 512 + k];
        float wf = Wh[((1 * 512) + jg) * 512 + k];
        float wg = Wh[((2 * 512) + jg) * 512 + k];
        float wo = Wh[((3 * 512) + jg) * 512 + k];
        ulonglong2 v;
        v.x = pk2(wi, wf);
        v.y = pk2(wg, wo);
        wS[idx] = v;
    }
    __syncthreads();

    const bool fin    = (tid < 256);
    const int  jg_fin = j0 + w;                 // valid when fin (w<8): unit = warp id
    float* hbufs = g_h + d * 2 * 512 * 32;
    float  c = 0.0f;

    // prefetch xp for step 0
    float xp_i = 0.f, xp_f = 0.f, xp_g = 0.f, xp_o = 0.f;
    if (fin) {
        const int tt0 = d ? 511 : 0;
        const float* xpp = g_xp + (((size_t)d * 512 + tt0) * 2048 + (size_t)jg_fin * 4) * 32 + lane;
        xp_i = xpp[0]; xp_f = xpp[32]; xp_g = xpp[64]; xp_o = xpp[96];
    }

    for (int s = 0; s < 512; s++) {
        const int tt = d ? (511 - s) : s;

        // ---- broadcast h_prev (buf s&1) into smem (4096 float4, 8 per thread)
        const float4* hsrc = (const float4*)(hbufs + (s & 1) * 16384);
        float4* hdst = (float4*)hS;
        #pragma unroll
        for (int i = 0; i < 8; i++)
            hdst[tid + i * 512] = hsrc[tid + i * 512];
        __syncthreads();

        // ---- partial gate accumulation over this warp's k-range [32w, 32w+32)
        ulonglong2 acc[8];
        #pragma unroll
        for (int j = 0; j < 8; j++) { acc[j].x = 0ull; acc[j].y = 0ull; }

        const int kbase = w * 32;
        #pragma unroll 4
        for (int kl = 0; kl < 32; kl++) {
            int k = kbase + kl;
            float hk = hS[k * 32 + lane];
            unsigned long long hh = pk2(hk, hk);
            const ulonglong2* wp = wS + k * 8;
            #pragma unroll
            for (int j = 0; j < 8; j++) {
                ulonglong2 wv = wp[j];
                fma2(acc[j].x, hh, wv.x);
                fma2(acc[j].y, hh, wv.y);
            }
        }

        // ---- stage partials: red[w][j][0/1][lane]
        #pragma unroll
        for (int j = 0; j < 8; j++) {
            red[(((w * 8 + j) * 2) + 0) * 32 + lane] = acc[j].x;
            red[(((w * 8 + j) * 2) + 1) * 32 + lane] = acc[j].y;
        }
        __syncthreads();

        if (fin) {
            unsigned long long s0 = 0ull, s1 = 0ull;
            #pragma unroll
            for (int ww = 0; ww < 16; ww++) {
                add2(s0, red[(((ww * 8 + w) * 2) + 0) * 32 + lane]);
                add2(s1, red[(((ww * 8 + w) * 2) + 1) * 32 + lane]);
            }
            float gi, gf, gg, go;
            upk2(s0, gi, gf);
            upk2(s1, gg, go);

            gi += xp_i; gf += xp_f; gg += xp_g; go += xp_o;
            gi = sigmoidf_(gi);
            gf = sigmoidf_(gf);
            go = sigmoidf_(go);
            gg = tanh_fast(gg);
            c = gf * c + gi * gg;
            float h = go * tanh_fast(c);

            // h -> next buffer (coalesced: [k][b]); output (write-through)
            hbufs[((s + 1) & 1) * 16384 + jg_fin * 32 + lane] = h;
            out[((size_t)lane * 512 + tt) * 1024 + d * 512 + jg_fin] = h;

            // ---- prefetch xp for step s+1 (DRAM latency overlaps the barrier spin)
            if (s + 1 < 512) {
                const int ttn = d ? (510 - s) : (s + 1);
                const float* xpp = g_xp + (((size_t)d * 512 + ttn) * 2048 + (size_t)jg_fin * 4) * 32 + lane;
                xp_i = xpp[0]; xp_f = xpp[32]; xp_g = xpp[64]; xp_o = xpp[96];
            }
        }

        // ---- grid-wide barrier (all 128 blocks resident)
        __syncthreads();
        if (tid == 0) {
            __threadfence();
            atomicAdd(&g_bar_count, 1u);
            unsigned target = (unsigned)(s + 1) * (unsigned)nb;
            while (*(volatile unsigned*)&g_bar_count < target) { }
            __threadfence();
        }
        __syncthreads();
    }
}

// ==================================================================================
extern "C" void kernel_launch(void* const* d_in, const int* in_sizes, int n_in,
                              void* d_out, int out_size)
{
    const float* x    = (const float*)d_in[0];
    const float* Wihf = (const float*)d_in[1];
    const float* Whhf = (const float*)d_in[2];
    const float* bf   = (const float*)d_in[3];
    const float* Wihb = (const float*)d_in[4];
    const float* Whhb = (const float*)d_in[5];
    const float* bb   = (const float*)d_in[6];
    float* out = (float*)d_out;

    cudaFuncSetAttribute(k_xproj, cudaFuncAttributeMaxDynamicSharedMemorySize, XPROJ_SMEM);
    cudaFuncSetAttribute(k_recur, cudaFuncAttributeMaxDynamicSharedMemorySize, RECUR_SMEM);

    k_init<<<256, 256>>>();
    k_xproj<<<dim3(16, 32, 2), 256, XPROJ_SMEM>>>(x, Wihf, bf, Wihb, bb);
    k_recur<<<128, 512, RECUR_SMEM>>>(Whhf, Whhb, out);
}

// round 5
// speedup vs baseline: 1.0835x; 1.0835x over previous
#include <cuda_runtime.h>
#include <cstdint>
#include <cstddef>

// Problem constants
#define NB 32
#define NT 512
#define NI 256
#define NH 512

// -------------------- device scratch (no allocations allowed) --------------------
// xp layout: [d][t][row(2048)][b(32)], row = unit*4 + gate  (gate: 0=i,1=f,2=g,3=o)
__device__ float    g_xp[2u * 512u * 2048u * 32u];   // 268 MB
// h double buffer per direction: [d][buf][k(512)][b(32)]
__device__ float    g_h[2 * 2 * 512 * 32];
__device__ unsigned g_bar_count;

// -------------------- f32x2 helpers --------------------
__device__ __forceinline__ unsigned long long pk2(float a, float b) {
    unsigned long long r;
    asm("mov.b64 %0, {%1,%2};" : "=l"(r) : "f"(a), "f"(b));
    return r;
}
__device__ __forceinline__ void upk2(unsigned long long v, float& a, float& b) {
    asm("mov.b64 {%0,%1}, %2;" : "=f"(a), "=f"(b) : "l"(v));
}
__device__ __forceinline__ void fma2(unsigned long long& d, unsigned long long a, unsigned long long b) {
    asm("fma.rn.f32x2 %0, %1, %2, %0;" : "+l"(d) : "l"(a), "l"(b));
}
__device__ __forceinline__ void add2(unsigned long long& d, unsigned long long a) {
    asm("add.rn.f32x2 %0, %0, %1;" : "+l"(d) : "l"(a));
}

__device__ __forceinline__ float sigmoidf_(float x) {
    return 1.0f / (1.0f + __expf(-x));
}
__device__ __forceinline__ float tanh_fast(float x) {
    float r;
    asm("tanh.approx.f32 %0, %1;" : "=f"(r) : "f"(x));
    return r;
}

// ==================================================================================
// init: zero h buffers, reset barrier counter (runs every launch -> deterministic)
// ==================================================================================
__global__ void k_init() {
    int t = blockIdx.x * blockDim.x + threadIdx.x;
    if (t == 0) g_bar_count = 0u;
    if (t < 2 * 2 * 512 * 32) g_h[t] = 0.0f;
}

// ==================================================================================
// Phase A: input projections.  xp[d][t][row][b] = sum_i x[b][t][i]*W_ih[d][wrow][i] + bias
// where row = unit*4+gate and wrow = gate*512 + unit  (wrow = (row&3)*512 + (row>>2)).
// Block: (t-chunk of 32) x (64 rows) x (direction).  256 threads, 8 warps.
// Warp w computes local rows w*8..w*8+7 (4 f32x2 pairs), lane = batch.
// ==================================================================================
#define XPROJ_SMEM (65536 + 64 * 33 * 16)  // 64KB packed weights + padded x tile

__global__ __launch_bounds__(256, 2) void k_xproj(
    const float* __restrict__ x,
    const float* __restrict__ Wf, const float* __restrict__ bf,
    const float* __restrict__ Wb, const float* __restrict__ bb)
{
    extern __shared__ char smem[];
    unsigned long long* sW = (unsigned long long*)smem;        // [256][32] u64 pairs (64KB)
    float*              fW = (float*)smem;                     // alias: fW[k*64 + lr]
    float4*             sX = (float4*)(smem + 65536);          // [k4(64)*33 + b] padded

    const int d    = blockIdx.z;
    const float* W    = d ? Wb : Wf;
    const float* bias = d ? bb : bf;
    const int R0   = blockIdx.y * 64;
    const int t0   = blockIdx.x * 32;
    const int tid  = threadIdx.x;
    const int lane = tid & 31;
    const int w    = tid >> 5;

    // ---- load + pack weight slice: fW[k*64 + lr] = W[wrow(R0+lr)][k]
    {
        int lr   = tid & 63;
        int kb   = (tid >> 6) * 64;
        int grow = R0 + lr;
        int wrow = ((grow & 3) << 9) + (grow >> 2);
        const float* src = W + wrow * 256 + kb;
        #pragma unroll 8
        for (int k = 0; k < 64; k++)
            fW[(kb + k) * 64 + lr] = src[k];
    }

    // ---- per-thread bias values for its 8 rows (hoisted out of t loop)
    float bv[8];
    #pragma unroll
    for (int r = 0; r < 8; r++) {
        int grow = R0 + w * 8 + r;
        bv[r] = bias[((grow & 3) << 9) + (grow >> 2)];
    }
    __syncthreads();

    for (int tl = 0; tl < 32; tl++) {
        int t = t0 + tl;
        __syncthreads();  // previous tile fully consumed
        // ---- load x tile: sX[k4*33 + b] = x[b][t][k4*4 .. +3]
        #pragma unroll
        for (int bi = 0; bi < 4; bi++) {
            int b = w + bi * 8;
            #pragma unroll
            for (int kh = 0; kh < 2; kh++) {
                int k4 = kh * 32 + lane;
                float4 v = *(const float4*)(x + ((size_t)(b * 512 + t)) * 256 + k4 * 4);
                sX[k4 * 33 + b] = v;
            }
        }
        __syncthreads();

        unsigned long long acc0 = 0, acc1 = 0, acc2 = 0, acc3 = 0;
        const unsigned long long* wbase = sW + w * 4;
        #pragma unroll 4
        for (int k4 = 0; k4 < 64; k4++) {
            float4 xv = sX[k4 * 33 + lane];
            #pragma unroll
            for (int kk = 0; kk < 4; kk++) {
                float xs = (&xv.x)[kk];
                unsigned long long hh = pk2(xs, xs);
                const unsigned long long* wp = wbase + (k4 * 4 + kk) * 32;
                ulonglong2 wa = *(const ulonglong2*)(wp);
                ulonglong2 wc = *(const ulonglong2*)(wp + 2);
                fma2(acc0, hh, wa.x);
                fma2(acc1, hh, wa.y);
                fma2(acc2, hh, wc.x);
                fma2(acc3, hh, wc.y);
            }
        }

        // ---- store 8 rows (coalesced over lanes = batch)
        float* outp = g_xp + ((((size_t)d * 512 + t) * 2048) + R0) * 32 + lane;
        float f0, f1;
        upk2(acc0, f0, f1);
        outp[(w * 8 + 0) * 32] = f0 + bv[0];
        outp[(w * 8 + 1) * 32] = f1 + bv[1];
        upk2(acc1, f0, f1);
        outp[(w * 8 + 2) * 32] = f0 + bv[2];
        outp[(w * 8 + 3) * 32] = f1 + bv[3];
        upk2(acc2, f0, f1);
        outp[(w * 8 + 4) * 32] = f0 + bv[4];
        outp[(w * 8 + 5) * 32] = f1 + bv[5];
        upk2(acc3, f0, f1);
        outp[(w * 8 + 6) * 32] = f0 + bv[6];
        outp[(w * 8 + 7) * 32] = f1 + bv[7];
    }
}

// ==================================================================================
// Phase B: persistent recurrent kernel (v3: 256 threads, h straight to registers).
// 128 blocks, 96KB smem, grid <= #SMs => 1 block/SM, all co-resident, barrier safe.
// Block bid: d = bid>>6, owns hidden units j0 = (bid&63)*8 .. +8 of that direction.
// Compute: warp w handles k-range [64w, 64w+64) for all 8 units x 4 gates (f32x2),
// lane = batch. h slice is loaded global->registers in 4 software-pipelined batches
// of 16 (per-k loads are one coalesced 128B line; no smem stage, no pre-compute sync).
// Cross-warp (8-way) reduce via smem. Finalize: warp = unit, lane = batch; c in reg.
// xp for step s+1 prefetched BEFORE the grid barrier (DRAM latency overlaps spin).
// ==================================================================================
#define RECUR_SMEM (65536 + 32768)  // W_hh pairs (64KB) + reduce staging (32KB)

__global__ __launch_bounds__(256, 1) void k_recur(
    const float* __restrict__ Whf,
    const float* __restrict__ Whb,
    float* __restrict__ out)
{
    extern __shared__ char smem[];
    ulonglong2*         wS  = (ulonglong2*)smem;                      // [512*8]  64KB
    unsigned long long* red = (unsigned long long*)(smem + 65536);    // [8][8][2][32] 32KB

    const int bid  = blockIdx.x;
    const int d    = bid >> 6;
    const int j0   = (bid & 63) * 8;
    const int tid  = threadIdx.x;
    const int lane = tid & 31;
    const int w    = tid >> 5;
    const int nb   = gridDim.x;
    const float* Wh = d ? Whb : Whf;

    // ---- load + pack W_hh slice: wS[k*8+j] = { (wi,wf), (wg,wo) } for unit j0+j
    for (int idx = tid; idx < 512 * 8; idx += 256) {
        int k  = idx >> 3;
        int j  = idx & 7;
        int jg = j0 + j;
        float wi = Wh[((0 * 512) + jg) * 512 + k];
        float wf = Wh[((1 * 512) + jg) * 512 + k];
        float wg = Wh[((2 * 512) + jg) * 512 + k];
        float wo = Wh[((3 * 512) + jg) * 512 + k];
        ulonglong2 v;
        v.x = pk2(wi, wf);
        v.y = pk2(wg, wo);
        wS[idx] = v;
    }
    __syncthreads();

    const int jg_fin = j0 + w;                  // finalize role: unit = warp id, batch = lane
    float* hbufs = g_h + d * 2 * 512 * 32;
    float  c = 0.0f;
    const int kbase = w * 64;

    // prefetch xp for step 0
    float xp_i, xp_f, xp_g, xp_o;
    {
        const int tt0 = d ? 511 : 0;
        const float* xpp = g_xp + (((size_t)d * 512 + tt0) * 2048 + (size_t)jg_fin * 4) * 32 + lane;
        xp_i = xpp[0]; xp_f = xpp[32]; xp_g = xpp[64]; xp_o = xpp[96];
    }

    for (int s = 0; s < 512; s++) {
        const int tt = d ? (511 - s) : s;

        // ---- h slice for this warp: global -> registers, 4 pipelined batches of 16
        const float* hsrc = hbufs + (s & 1) * 16384 + kbase * 32 + lane;

        float hb0[16], hb1[16];
        #pragma unroll
        for (int i = 0; i < 16; i++) hb0[i] = hsrc[i * 32];          // batch 0

        ulonglong2 acc[8];
        #pragma unroll
        for (int j = 0; j < 8; j++) { acc[j].x = 0ull; acc[j].y = 0ull; }

        #pragma unroll
        for (int kb = 0; kb < 4; kb++) {
            float* cur = (kb & 1) ? hb1 : hb0;
            float* nxt = (kb & 1) ? hb0 : hb1;
            if (kb < 3) {
                #pragma unroll
                for (int i = 0; i < 16; i++)
                    nxt[i] = hsrc[((kb + 1) * 16 + i) * 32];         // prefetch next batch
            }
            const ulonglong2* wp = wS + (kbase + kb * 16) * 8;
            #pragma unroll
            for (int i = 0; i < 16; i++) {
                unsigned long long hh = pk2(cur[i], cur[i]);
                const ulonglong2* wk = wp + i * 8;
                #pragma unroll
                for (int j = 0; j < 8; j++) {
                    ulonglong2 wv = wk[j];
                    fma2(acc[j].x, hh, wv.x);
                    fma2(acc[j].y, hh, wv.y);
                }
            }
        }

        // ---- stage partials: red[w][j][0/1][lane]
        #pragma unroll
        for (int j = 0; j < 8; j++) {
            red[(((w * 8 + j) * 2) + 0) * 32 + lane] = acc[j].x;
            red[(((w * 8 + j) * 2) + 1) * 32 + lane] = acc[j].y;
        }
        __syncthreads();

        // ---- finalize: warp w = unit j0+w, lane = batch
        unsigned long long s0 = 0ull, s1 = 0ull;
        #pragma unroll
        for (int ww = 0; ww < 8; ww++) {
            add2(s0, red[(((ww * 8 + w) * 2) + 0) * 32 + lane]);
            add2(s1, red[(((ww * 8 + w) * 2) + 1) * 32 + lane]);
        }
        float gi, gf, gg, go;
        upk2(s0, gi, gf);
        upk2(s1, gg, go);

        gi += xp_i; gf += xp_f; gg += xp_g; go += xp_o;
        gi = sigmoidf_(gi);
        gf = sigmoidf_(gf);
        go = sigmoidf_(go);
        gg = tanh_fast(gg);
        c = gf * c + gi * gg;
        float h = go * tanh_fast(c);

        // h -> next buffer (coalesced: [k][b]); output (write-through)
        hbufs[((s + 1) & 1) * 16384 + jg_fin * 32 + lane] = h;
        out[((size_t)lane * 512 + tt) * 1024 + d * 512 + jg_fin] = h;

        // ---- prefetch xp for step s+1 (DRAM latency overlaps the barrier spin)
        if (s + 1 < 512) {
            const int ttn = d ? (510 - s) : (s + 1);
            const float* xpp = g_xp + (((size_t)d * 512 + ttn) * 2048 + (size_t)jg_fin * 4) * 32 + lane;
            xp_i = xpp[0]; xp_f = xpp[32]; xp_g = xpp[64]; xp_o = xpp[96];
        }

        // ---- grid-wide barrier (all 128 blocks resident)
        __syncthreads();
        if (tid == 0) {
            __threadfence();
            atomicAdd(&g_bar_count, 1u);
            unsigned target = (unsigned)(s + 1) * (unsigned)nb;
            while (*(volatile unsigned*)&g_bar_count < target) { }
            __threadfence();
        }
        __syncthreads();
    }
}

// ==================================================================================
extern "C" void kernel_launch(void* const* d_in, const int* in_sizes, int n_in,
                              void* d_out, int out_size)
{
    const float* x    = (const float*)d_in[0];
    const float* Wihf = (const float*)d_in[1];
    const float* Whhf = (const float*)d_in[2];
    const float* bf   = (const float*)d_in[3];
    const float* Wihb = (const float*)d_in[4];
    const float* Whhb = (const float*)d_in[5];
    const float* bb   = (const float*)d_in[6];
    float* out = (float*)d_out;

    cudaFuncSetAttribute(k_xproj, cudaFuncAttributeMaxDynamicSharedMemorySize, XPROJ_SMEM);
    cudaFuncSetAttribute(k_recur, cudaFuncAttributeMaxDynamicSharedMemorySize, RECUR_SMEM);

    k_init<<<256, 256>>>();
    k_xproj<<<dim3(16, 32, 2), 256, XPROJ_SMEM>>>(x, Wihf, bf, Wihb, bb);
    k_recur<<<128, 256, RECUR_SMEM>>>(Whhf, Whhb, out);
}